// round 2
// baseline (speedup 1.0000x reference)
#include <cuda_runtime.h>
#include <cuda_bf16.h>
#include <math.h>

// ---------------- problem constants ----------------
#define BATCH   4
#define LSEQ    1024
#define NMELS   80
#define DMODEL  512
#define NLAYER  6
#define DSTATE  16
#define DINNER  1024
#define DTRANK  32
#define DCONV   4
#define NROWS   (BATCH * LSEQ)          // 4096

// ---------------- scratch (static device memory; no allocation) ----------------
__device__ float g_h   [NROWS * DMODEL];        //  8 MB residual stream
__device__ float g_xn  [NROWS * DMODEL];        //  8 MB normalized
__device__ float g_xr  [NROWS * 2 * DINNER];    // 32 MB inproj out (u | res)
__device__ float g_u   [NROWS * DINNER];        // 16 MB conv+silu out
__device__ float g_xdbl[NROWS * 64];            //  1 MB (dt | B | C)
__device__ float g_delta[NROWS * DINNER];       // 16 MB
__device__ float g_y   [NROWS * DINNER];        // 16 MB

// ---------------- generic NT SGEMM: C[m,n] = sum_k A[m,k]*W[n,k] ----------------
// A: M x K (row stride lda), W: N x K (row stride ldw), C: M x ldc.
// Requires: M % 64 == 0, K % 16 == 0.  N arbitrary (guarded).
// epilogue: v = acc (+ bias[n]) (+ addsrc[m*ldc+n]); act==1 -> softplus(v)
__global__ __launch_bounds__(256, 4)
void gemm_nt(const float* __restrict__ A, int lda,
             const float* __restrict__ W, int ldw,
             float* __restrict__ C, int ldc,
             int N, int K,
             const float* __restrict__ bias,
             const float* __restrict__ addsrc,
             int act)
{
    __shared__ float As[64][17];
    __shared__ float Bs[64][17];

    const int tid = threadIdx.x;
    const int r0  = blockIdx.y * 64;
    const int n0  = blockIdx.x * 64;
    const int ty  = tid >> 4;        // 0..15
    const int tx  = tid & 15;        // 0..15
    const int ty4 = ty * 4;
    const int tx4 = tx * 4;

    float acc[4][4];
#pragma unroll
    for (int i = 0; i < 4; i++)
#pragma unroll
        for (int j = 0; j < 4; j++) acc[i][j] = 0.f;

    for (int kk = 0; kk < K; kk += 16) {
        // load 64x16 tiles (4 elems / thread)
#pragma unroll
        for (int p = 0; p < 4; p++) {
            int li  = tid + p * 256;
            int row = li >> 4;
            int col = li & 15;
            As[row][col] = A[(size_t)(r0 + row) * lda + kk + col];
            int nr = n0 + row;
            Bs[row][col] = (nr < N) ? W[(size_t)nr * ldw + kk + col] : 0.f;
        }
        __syncthreads();

#pragma unroll
        for (int k = 0; k < 16; k++) {
            float a0 = As[ty4 + 0][k], a1 = As[ty4 + 1][k];
            float a2 = As[ty4 + 2][k], a3 = As[ty4 + 3][k];
            float b0 = Bs[tx4 + 0][k], b1 = Bs[tx4 + 1][k];
            float b2 = Bs[tx4 + 2][k], b3 = Bs[tx4 + 3][k];
            acc[0][0] = fmaf(a0, b0, acc[0][0]); acc[0][1] = fmaf(a0, b1, acc[0][1]);
            acc[0][2] = fmaf(a0, b2, acc[0][2]); acc[0][3] = fmaf(a0, b3, acc[0][3]);
            acc[1][0] = fmaf(a1, b0, acc[1][0]); acc[1][1] = fmaf(a1, b1, acc[1][1]);
            acc[1][2] = fmaf(a1, b2, acc[1][2]); acc[1][3] = fmaf(a1, b3, acc[1][3]);
            acc[2][0] = fmaf(a2, b0, acc[2][0]); acc[2][1] = fmaf(a2, b1, acc[2][1]);
            acc[2][2] = fmaf(a2, b2, acc[2][2]); acc[2][3] = fmaf(a2, b3, acc[2][3]);
            acc[3][0] = fmaf(a3, b0, acc[3][0]); acc[3][1] = fmaf(a3, b1, acc[3][1]);
            acc[3][2] = fmaf(a3, b2, acc[3][2]); acc[3][3] = fmaf(a3, b3, acc[3][3]);
        }
        __syncthreads();
    }

#pragma unroll
    for (int i = 0; i < 4; i++) {
        int m = r0 + ty4 + i;
#pragma unroll
        for (int j = 0; j < 4; j++) {
            int n = n0 + tx4 + j;
            if (n < N) {
                float v = acc[i][j];
                if (bias)   v += bias[n];
                if (addsrc) v += addsrc[(size_t)m * ldc + n];
                if (act == 1) v = (v > 20.f) ? v : log1pf(__expf(v));
                C[(size_t)m * ldc + n] = v;
            }
        }
    }
}

// ---------------- RMSNorm over last dim (=512), one block per row ----------------
__global__ void rmsnorm_k(const float* __restrict__ x, const float* __restrict__ w,
                          float* __restrict__ o)
{
    const int row = blockIdx.x;
    const int tid = threadIdx.x;          // 256 threads, 2 elems each
    const float* xr = x + (size_t)row * DMODEL;
    float v0 = xr[tid];
    float v1 = xr[tid + 256];
    float s  = v0 * v0 + v1 * v1;
#pragma unroll
    for (int off = 16; off; off >>= 1) s += __shfl_xor_sync(0xffffffffu, s, off);
    __shared__ float ws[8];
    if ((tid & 31) == 0) ws[tid >> 5] = s;
    __syncthreads();
    if (tid < 32) {
        float t = (tid < 8) ? ws[tid] : 0.f;
#pragma unroll
        for (int off = 4; off; off >>= 1) t += __shfl_xor_sync(0xffffffffu, t, off);
        if (tid == 0) ws[0] = t;
    }
    __syncthreads();
    float scale = rsqrtf(ws[0] * (1.f / DMODEL) + 1e-5f);
    float* orow = o + (size_t)row * DMODEL;
    orow[tid]       = v0 * scale * w[tid];
    orow[tid + 256] = v1 * scale * w[tid + 256];
}

// ---------------- causal depthwise conv (k=4) + bias + silu ----------------
// reads u-half of xr (cols 0..DINNER-1 of 2*DINNER row), writes g_u (b,l,d)
__global__ void conv_silu_k(const float* __restrict__ xr,
                            const float* __restrict__ cw,
                            const float* __restrict__ cb,
                            float* __restrict__ u)
{
    int g = blockIdx.x * blockDim.x + threadIdx.x;   // b*L*D + l*D + d
    int d = g & (DINNER - 1);
    int t = (g >> 10) & (LSEQ - 1);
    int b = g >> 20;
    const float* base = xr + ((size_t)(b * LSEQ + t)) * (2 * DINNER) + d;
    float w0 = cw[d * 4 + 0], w1 = cw[d * 4 + 1], w2 = cw[d * 4 + 2], w3 = cw[d * 4 + 3];
    float acc = cb[d] + base[0] * w3;
    if (t >= 1) acc = fmaf(base[-(2 * DINNER)],     w2, acc);
    if (t >= 2) acc = fmaf(base[-(4 * DINNER)],     w1, acc);
    if (t >= 3) acc = fmaf(base[-(6 * DINNER)],     w0, acc);
    u[g] = acc / (1.f + __expf(-acc));   // silu
}

// ---------------- selective scan ----------------
// thread g -> (b, d, n): n = g&15. h recurrence per (b,d,n); 16-lane shfl reduce for y.
// fused: y = (sum_n h*C) + u*Dp, then y *= silu(res); res = xr[..., DINNER + d]
__global__ __launch_bounds__(256, 8)
void scan_k(const float* __restrict__ delta, const float* __restrict__ u,
            const float* __restrict__ xdbl,  const float* __restrict__ xr,
            const float* __restrict__ A_log, const float* __restrict__ Dp,
            float* __restrict__ y)
{
    int g  = blockIdx.x * 256 + threadIdx.x;   // 65536 total
    int n  = g & 15;
    int bd = g >> 4;                 // 0..4095
    int d  = bd & (DINNER - 1);
    int b  = bd >> 10;

    const float a  = -__expf(A_log[d * DSTATE + n]);
    const float Dv = Dp[d];

    const size_t rowsz = (size_t)LSEQ;
    const float* dp = delta + ((size_t)b * rowsz) * DINNER + d;
    const float* up = u     + ((size_t)b * rowsz) * DINNER + d;
    const float* rp = xr    + ((size_t)b * rowsz) * (2 * DINNER) + DINNER + d;
    const float* xp = xdbl  + ((size_t)b * rowsz) * 64;
    float*       yp = y     + ((size_t)b * rowsz) * DINNER + d;

    float h = 0.f;
#pragma unroll 2
    for (int t = 0; t < LSEQ; t++) {
        float dv = dp[(size_t)t << 10];
        float uv = up[(size_t)t << 10];
        float Bv = xp[t * 64 + 32 + n];
        float Cv = xp[t * 64 + 48 + n];
        float dA = __expf(dv * a);
        h = fmaf(dA, h, dv * Bv * uv);
        float p = h * Cv;
        p += __shfl_xor_sync(0xffffffffu, p, 8);
        p += __shfl_xor_sync(0xffffffffu, p, 4);
        p += __shfl_xor_sync(0xffffffffu, p, 2);
        p += __shfl_xor_sync(0xffffffffu, p, 1);
        if (n == 0) {
            float yv = fmaf(uv, Dv, p);
            float r  = rp[(size_t)t << 11];
            yv *= r / (1.f + __expf(-r));     // * silu(res)
            yp[(size_t)t << 10] = yv;
        }
    }
}

// ---------------- host driver ----------------
extern "C" void kernel_launch(void* const* d_in, const int* in_sizes, int n_in,
                              void* d_out, int out_size)
{
    const float* x        = (const float*)d_in[0];
    const float* in_w     = (const float*)d_in[1];
    const float* in_b     = (const float*)d_in[2];
    const float* norm_w   = (const float*)d_in[3];
    const float* inproj_w = (const float*)d_in[4];
    const float* conv_w   = (const float*)d_in[5];
    const float* conv_b   = (const float*)d_in[6];
    const float* xproj_w  = (const float*)d_in[7];
    const float* dt_w     = (const float*)d_in[8];
    const float* dt_b     = (const float*)d_in[9];
    const float* A_log    = (const float*)d_in[10];
    const float* Dp       = (const float*)d_in[11];
    const float* outproj_w= (const float*)d_in[12];
    const float* normf_w  = (const float*)d_in[13];
    const float* out_w    = (const float*)d_in[14];
    float* out = (float*)d_out;

    float *h, *xn, *xrb, *u, *xdbl, *delta, *y;
    cudaGetSymbolAddress((void**)&h,     g_h);
    cudaGetSymbolAddress((void**)&xn,    g_xn);
    cudaGetSymbolAddress((void**)&xrb,   g_xr);
    cudaGetSymbolAddress((void**)&u,     g_u);
    cudaGetSymbolAddress((void**)&xdbl,  g_xdbl);
    cudaGetSymbolAddress((void**)&delta, g_delta);
    cudaGetSymbolAddress((void**)&y,     g_y);

    const dim3 blk(256);
    const int MB = NROWS / 64;   // 64 row-blocks

    // input projection: h = x @ in_w^T + in_b   (4096 x 512, K=80)
    gemm_nt<<<dim3((DMODEL + 63) / 64, MB), blk>>>(x, NMELS, in_w, NMELS,
                                                   h, DMODEL, DMODEL, NMELS,
                                                   in_b, nullptr, 0);

    for (int i = 0; i < NLAYER; i++) {
        // rmsnorm
        rmsnorm_k<<<NROWS, 256>>>(h, norm_w + (size_t)i * DMODEL, xn);
        // inproj: xr = xn @ inproj_w^T   (4096 x 2048, K=512)
        gemm_nt<<<dim3(2 * DINNER / 64, MB), blk>>>(xn, DMODEL,
            inproj_w + (size_t)i * 2 * DINNER * DMODEL, DMODEL,
            xrb, 2 * DINNER, 2 * DINNER, DMODEL, nullptr, nullptr, 0);
        // conv + silu -> u
        conv_silu_k<<<(NROWS * DINNER) / 256, 256>>>(xrb,
            conv_w + (size_t)i * DINNER * DCONV, conv_b + (size_t)i * DINNER, u);
        // xproj: xdbl = u @ xproj_w^T   (4096 x 64, K=1024)
        gemm_nt<<<dim3(1, MB), blk>>>(u, DINNER,
            xproj_w + (size_t)i * 64 * DINNER, DINNER,
            xdbl, 64, 64, DINNER, nullptr, nullptr, 0);
        // delta = softplus(xdbl[:, :32] @ dt_w^T + dt_b)  (4096 x 1024, K=32)
        gemm_nt<<<dim3(DINNER / 64, MB), blk>>>(xdbl, 64,
            dt_w + (size_t)i * DINNER * DTRANK, DTRANK,
            delta, DINNER, DINNER, DTRANK,
            dt_b + (size_t)i * DINNER, nullptr, 1);
        // selective scan (+ *silu(res), +u*Dp) -> y
        scan_k<<<(NROWS * DSTATE) / 256, 256>>>(delta, u, xdbl, xrb,
            A_log + (size_t)i * DINNER * DSTATE, Dp + (size_t)i * DINNER, y);
        // outproj + residual: h = h + y @ outproj_w^T   (4096 x 512, K=1024)
        gemm_nt<<<dim3(DMODEL / 64, MB), blk>>>(y, DINNER,
            outproj_w + (size_t)i * DMODEL * DINNER, DINNER,
            h, DMODEL, DMODEL, DINNER, nullptr, h, 0);
    }

    // final norm + output projection (4096 x 80, K=512)
    rmsnorm_k<<<NROWS, 256>>>(h, normf_w, xn);
    gemm_nt<<<dim3((NMELS + 63) / 64, MB), blk>>>(xn, DMODEL, out_w, DMODEL,
                                                  out, NMELS, NMELS, DMODEL,
                                                  nullptr, nullptr, 0);
}

// round 3
// speedup vs baseline: 1.1135x; 1.1135x over previous
#include <cuda_runtime.h>
#include <cuda_bf16.h>
#include <math.h>

// ---------------- problem constants ----------------
#define BATCH   4
#define LSEQ    1024
#define NMELS   80
#define DMODEL  512
#define NLAYER  6
#define DSTATE  16
#define DINNER  1024
#define DTRANK  32
#define DCONV   4
#define NROWS   (BATCH * LSEQ)          // 4096

// ---------------- scratch (static device memory; no allocation) ----------------
__device__ float g_h   [NROWS * DMODEL];
__device__ float g_xn  [NROWS * DMODEL];
__device__ float g_xr  [NROWS * 2 * DINNER];
__device__ float g_u   [NROWS * DINNER];
__device__ float g_xdbl[NROWS * 64];
__device__ float g_delta[NROWS * DINNER];
__device__ float g_y   [NROWS * DINNER];

// =====================================================================
// Big NT SGEMM: C[m,n] = sum_k A[m,k] * W[n,k]
// 128x128 tile, k-block 8, 256 threads, 8x8 microtile, LDS.128 fragments,
// double-buffered smem. Requires M%128==0, N%128==0, K%8==0.
// epilogue: v = acc (+bias[n]) (+addsrc[m*ldc+n]); act==1 -> softplus
// =====================================================================
__global__ __launch_bounds__(256)
void gemm_nt_big(const float* __restrict__ A, int lda,
                 const float* __restrict__ W, int ldw,
                 float* __restrict__ C, int ldc,
                 int K,
                 const float* __restrict__ bias,
                 const float* __restrict__ addsrc,
                 int act)
{
    __shared__ float As[2][8][132];   // k-major, padded (132%4==0 keeps 16B align)
    __shared__ float Bs[2][8][132];

    const int tid  = threadIdx.x;
    const int r0   = blockIdx.y * 128;
    const int n0   = blockIdx.x * 128;
    const int lrow = tid >> 1;            // 0..127
    const int lk4  = (tid & 1) * 4;       // 0 or 4

    const float* Ap = A + (size_t)(r0 + lrow) * lda + lk4;
    const float* Wp = W + (size_t)(n0 + lrow) * ldw + lk4;

    const int ty8 = (tid >> 4) * 8;       // row offset in tile
    const int tx8 = (tid & 15) * 8;       // col offset in tile

    float acc[8][8];
#pragma unroll
    for (int i = 0; i < 8; i++)
#pragma unroll
        for (int j = 0; j < 8; j++) acc[i][j] = 0.f;

    // preload first tile
    {
        float4 av = *(const float4*)Ap;
        float4 bv = *(const float4*)Wp;
        As[0][lk4 + 0][lrow] = av.x; As[0][lk4 + 1][lrow] = av.y;
        As[0][lk4 + 2][lrow] = av.z; As[0][lk4 + 3][lrow] = av.w;
        Bs[0][lk4 + 0][lrow] = bv.x; Bs[0][lk4 + 1][lrow] = bv.y;
        Bs[0][lk4 + 2][lrow] = bv.z; Bs[0][lk4 + 3][lrow] = bv.w;
    }
    __syncthreads();

    int buf = 0;
    for (int kk = 0; kk < K; kk += 8) {
        const bool has_next = (kk + 8) < K;
        float4 anx, bnx;
        if (has_next) {
            anx = *(const float4*)(Ap + kk + 8);
            bnx = *(const float4*)(Wp + kk + 8);
        }

#pragma unroll
        for (int k = 0; k < 8; k++) {
            float a[8], b[8];
            *(float4*)&a[0] = *(const float4*)&As[buf][k][ty8];
            *(float4*)&a[4] = *(const float4*)&As[buf][k][ty8 + 4];
            *(float4*)&b[0] = *(const float4*)&Bs[buf][k][tx8];
            *(float4*)&b[4] = *(const float4*)&Bs[buf][k][tx8 + 4];
#pragma unroll
            for (int i = 0; i < 8; i++)
#pragma unroll
                for (int j = 0; j < 8; j++)
                    acc[i][j] = fmaf(a[i], b[j], acc[i][j]);
        }

        if (has_next) {
            const int nb = buf ^ 1;
            As[nb][lk4 + 0][lrow] = anx.x; As[nb][lk4 + 1][lrow] = anx.y;
            As[nb][lk4 + 2][lrow] = anx.z; As[nb][lk4 + 3][lrow] = anx.w;
            Bs[nb][lk4 + 0][lrow] = bnx.x; Bs[nb][lk4 + 1][lrow] = bnx.y;
            Bs[nb][lk4 + 2][lrow] = bnx.z; Bs[nb][lk4 + 3][lrow] = bnx.w;
        }
        __syncthreads();
        buf ^= 1;
    }

    // epilogue
#pragma unroll
    for (int i = 0; i < 8; i++) {
        const size_t off = (size_t)(r0 + ty8 + i) * ldc + n0 + tx8;
#pragma unroll
        for (int j = 0; j < 8; j++) {
            float v = acc[i][j];
            if (bias)   v += bias[n0 + tx8 + j];
            if (addsrc) v += addsrc[off + j];
            if (act == 1) v = (v > 20.f) ? v : log1pf(__expf(v));
            C[off + j] = v;
        }
    }
}

// ---------------- small NT SGEMM (64x64 tile) for N<128 cases ----------------
__global__ __launch_bounds__(256, 4)
void gemm_nt(const float* __restrict__ A, int lda,
             const float* __restrict__ W, int ldw,
             float* __restrict__ C, int ldc,
             int N, int K,
             const float* __restrict__ bias,
             const float* __restrict__ addsrc,
             int act)
{
    __shared__ float As[64][17];
    __shared__ float Bs[64][17];

    const int tid = threadIdx.x;
    const int r0  = blockIdx.y * 64;
    const int n0  = blockIdx.x * 64;
    const int ty4 = (tid >> 4) * 4;
    const int tx4 = (tid & 15) * 4;

    float acc[4][4];
#pragma unroll
    for (int i = 0; i < 4; i++)
#pragma unroll
        for (int j = 0; j < 4; j++) acc[i][j] = 0.f;

    for (int kk = 0; kk < K; kk += 16) {
#pragma unroll
        for (int p = 0; p < 4; p++) {
            int li  = tid + p * 256;
            int row = li >> 4;
            int col = li & 15;
            As[row][col] = A[(size_t)(r0 + row) * lda + kk + col];
            int nr = n0 + row;
            Bs[row][col] = (nr < N) ? W[(size_t)nr * ldw + kk + col] : 0.f;
        }
        __syncthreads();

#pragma unroll
        for (int k = 0; k < 16; k++) {
            float a0 = As[ty4 + 0][k], a1 = As[ty4 + 1][k];
            float a2 = As[ty4 + 2][k], a3 = As[ty4 + 3][k];
            float b0 = Bs[tx4 + 0][k], b1 = Bs[tx4 + 1][k];
            float b2 = Bs[tx4 + 2][k], b3 = Bs[tx4 + 3][k];
            acc[0][0] = fmaf(a0, b0, acc[0][0]); acc[0][1] = fmaf(a0, b1, acc[0][1]);
            acc[0][2] = fmaf(a0, b2, acc[0][2]); acc[0][3] = fmaf(a0, b3, acc[0][3]);
            acc[1][0] = fmaf(a1, b0, acc[1][0]); acc[1][1] = fmaf(a1, b1, acc[1][1]);
            acc[1][2] = fmaf(a1, b2, acc[1][2]); acc[1][3] = fmaf(a1, b3, acc[1][3]);
            acc[2][0] = fmaf(a2, b0, acc[2][0]); acc[2][1] = fmaf(a2, b1, acc[2][1]);
            acc[2][2] = fmaf(a2, b2, acc[2][2]); acc[2][3] = fmaf(a2, b3, acc[2][3]);
            acc[3][0] = fmaf(a3, b0, acc[3][0]); acc[3][1] = fmaf(a3, b1, acc[3][1]);
            acc[3][2] = fmaf(a3, b2, acc[3][2]); acc[3][3] = fmaf(a3, b3, acc[3][3]);
        }
        __syncthreads();
    }

#pragma unroll
    for (int i = 0; i < 4; i++) {
        int m = r0 + ty4 + i;
#pragma unroll
        for (int j = 0; j < 4; j++) {
            int n = n0 + tx4 + j;
            if (n < N) {
                float v = acc[i][j];
                if (bias)   v += bias[n];
                if (addsrc) v += addsrc[(size_t)m * ldc + n];
                if (act == 1) v = (v > 20.f) ? v : log1pf(__expf(v));
                C[(size_t)m * ldc + n] = v;
            }
        }
    }
}

// ---------------- RMSNorm over last dim (=512), one block per row ----------------
__global__ void rmsnorm_k(const float* __restrict__ x, const float* __restrict__ w,
                          float* __restrict__ o)
{
    const int row = blockIdx.x;
    const int tid = threadIdx.x;
    const float* xr = x + (size_t)row * DMODEL;
    float v0 = xr[tid];
    float v1 = xr[tid + 256];
    float s  = v0 * v0 + v1 * v1;
#pragma unroll
    for (int off = 16; off; off >>= 1) s += __shfl_xor_sync(0xffffffffu, s, off);
    __shared__ float ws[8];
    if ((tid & 31) == 0) ws[tid >> 5] = s;
    __syncthreads();
    if (tid < 32) {
        float t = (tid < 8) ? ws[tid] : 0.f;
#pragma unroll
        for (int off = 4; off; off >>= 1) t += __shfl_xor_sync(0xffffffffu, t, off);
        if (tid == 0) ws[0] = t;
    }
    __syncthreads();
    float scale = rsqrtf(ws[0] * (1.f / DMODEL) + 1e-5f);
    float* orow = o + (size_t)row * DMODEL;
    orow[tid]       = v0 * scale * w[tid];
    orow[tid + 256] = v1 * scale * w[tid + 256];
}

// ---------------- causal depthwise conv (k=4) + bias + silu ----------------
__global__ void conv_silu_k(const float* __restrict__ xr,
                            const float* __restrict__ cw,
                            const float* __restrict__ cb,
                            float* __restrict__ u)
{
    int g = blockIdx.x * blockDim.x + threadIdx.x;
    int d = g & (DINNER - 1);
    int t = (g >> 10) & (LSEQ - 1);
    int b = g >> 20;
    const float* base = xr + ((size_t)(b * LSEQ + t)) * (2 * DINNER) + d;
    float w0 = cw[d * 4 + 0], w1 = cw[d * 4 + 1], w2 = cw[d * 4 + 2], w3 = cw[d * 4 + 3];
    float acc = cb[d] + base[0] * w3;
    if (t >= 1) acc = fmaf(base[-(2 * DINNER)], w2, acc);
    if (t >= 2) acc = fmaf(base[-(4 * DINNER)], w1, acc);
    if (t >= 3) acc = fmaf(base[-(6 * DINNER)], w0, acc);
    u[g] = acc / (1.f + __expf(-acc));
}

// ---------------- selective scan ----------------
__global__ __launch_bounds__(256, 8)
void scan_k(const float* __restrict__ delta, const float* __restrict__ u,
            const float* __restrict__ xdbl,  const float* __restrict__ xr,
            const float* __restrict__ A_log, const float* __restrict__ Dp,
            float* __restrict__ y)
{
    int g  = blockIdx.x * 256 + threadIdx.x;
    int n  = g & 15;
    int bd = g >> 4;
    int d  = bd & (DINNER - 1);
    int b  = bd >> 10;

    const float a  = -__expf(A_log[d * DSTATE + n]);
    const float Dv = Dp[d];

    const float* dp = delta + ((size_t)b * LSEQ) * DINNER + d;
    const float* up = u     + ((size_t)b * LSEQ) * DINNER + d;
    const float* rp = xr    + ((size_t)b * LSEQ) * (2 * DINNER) + DINNER + d;
    const float* xp = xdbl  + ((size_t)b * LSEQ) * 64;
    float*       yp = y     + ((size_t)b * LSEQ) * DINNER + d;

    float h = 0.f;
#pragma unroll 2
    for (int t = 0; t < LSEQ; t++) {
        float dv = dp[(size_t)t << 10];
        float uv = up[(size_t)t << 10];
        float Bv = xp[t * 64 + 32 + n];
        float Cv = xp[t * 64 + 48 + n];
        float dA = __expf(dv * a);
        h = fmaf(dA, h, dv * Bv * uv);
        float p = h * Cv;
        p += __shfl_xor_sync(0xffffffffu, p, 8);
        p += __shfl_xor_sync(0xffffffffu, p, 4);
        p += __shfl_xor_sync(0xffffffffu, p, 2);
        p += __shfl_xor_sync(0xffffffffu, p, 1);
        if (n == 0) {
            float yv = fmaf(uv, Dv, p);
            float r  = rp[(size_t)t << 11];
            yv *= r / (1.f + __expf(-r));
            yp[(size_t)t << 10] = yv;
        }
    }
}

// ---------------- host driver ----------------
extern "C" void kernel_launch(void* const* d_in, const int* in_sizes, int n_in,
                              void* d_out, int out_size)
{
    const float* x        = (const float*)d_in[0];
    const float* in_w     = (const float*)d_in[1];
    const float* in_b     = (const float*)d_in[2];
    const float* norm_w   = (const float*)d_in[3];
    const float* inproj_w = (const float*)d_in[4];
    const float* conv_w   = (const float*)d_in[5];
    const float* conv_b   = (const float*)d_in[6];
    const float* xproj_w  = (const float*)d_in[7];
    const float* dt_w     = (const float*)d_in[8];
    const float* dt_b     = (const float*)d_in[9];
    const float* A_log    = (const float*)d_in[10];
    const float* Dp       = (const float*)d_in[11];
    const float* outproj_w= (const float*)d_in[12];
    const float* normf_w  = (const float*)d_in[13];
    const float* out_w    = (const float*)d_in[14];
    float* out = (float*)d_out;

    float *h, *xn, *xrb, *u, *xdbl, *delta, *y;
    cudaGetSymbolAddress((void**)&h,     g_h);
    cudaGetSymbolAddress((void**)&xn,    g_xn);
    cudaGetSymbolAddress((void**)&xrb,   g_xr);
    cudaGetSymbolAddress((void**)&u,     g_u);
    cudaGetSymbolAddress((void**)&xdbl,  g_xdbl);
    cudaGetSymbolAddress((void**)&delta, g_delta);
    cudaGetSymbolAddress((void**)&y,     g_y);

    const dim3 blk(256);
    const int MB128 = NROWS / 128;   // 32 row-blocks for big gemm
    const int MB64  = NROWS / 64;    // 64 row-blocks for small gemm

    // input projection: h = x @ in_w^T + in_b  (M=4096, N=512, K=80) — big gemm
    gemm_nt_big<<<dim3(DMODEL / 128, MB128), blk>>>(x, NMELS, in_w, NMELS,
                                                    h, DMODEL, NMELS,
                                                    in_b, nullptr, 0);

    for (int i = 0; i < NLAYER; i++) {
        rmsnorm_k<<<NROWS, 256>>>(h, norm_w + (size_t)i * DMODEL, xn);

        // inproj: (4096 x 2048, K=512)
        gemm_nt_big<<<dim3(2 * DINNER / 128, MB128), blk>>>(xn, DMODEL,
            inproj_w + (size_t)i * 2 * DINNER * DMODEL, DMODEL,
            xrb, 2 * DINNER, DMODEL, nullptr, nullptr, 0);

        conv_silu_k<<<(NROWS * DINNER) / 256, 256>>>(xrb,
            conv_w + (size_t)i * DINNER * DCONV, conv_b + (size_t)i * DINNER, u);

        // xproj: (4096 x 64, K=1024) — N too small for big tile
        gemm_nt<<<dim3(1, MB64), blk>>>(u, DINNER,
            xproj_w + (size_t)i * 64 * DINNER, DINNER,
            xdbl, 64, 64, DINNER, nullptr, nullptr, 0);

        // delta = softplus(dt @ dt_w^T + dt_b)  (4096 x 1024, K=32)
        gemm_nt_big<<<dim3(DINNER / 128, MB128), blk>>>(xdbl, 64,
            dt_w + (size_t)i * DINNER * DTRANK, DTRANK,
            delta, DINNER, DTRANK,
            dt_b + (size_t)i * DINNER, nullptr, 1);

        scan_k<<<(NROWS * DSTATE) / 256, 256>>>(delta, u, xdbl, xrb,
            A_log + (size_t)i * DINNER * DSTATE, Dp + (size_t)i * DINNER, y);

        // outproj + residual: (4096 x 512, K=1024)
        gemm_nt_big<<<dim3(DMODEL / 128, MB128), blk>>>(y, DINNER,
            outproj_w + (size_t)i * DMODEL * DINNER, DINNER,
            h, DMODEL, DINNER, nullptr, h, 0);
    }

    rmsnorm_k<<<NROWS, 256>>>(h, normf_w, xn);
    // final: (4096 x 80, K=512) — small gemm (N=80)
    gemm_nt<<<dim3((NMELS + 63) / 64, MB64), blk>>>(xn, DMODEL, out_w, DMODEL,
                                                    out, NMELS, NMELS, DMODEL,
                                                    nullptr, nullptr, 0);
}

// round 4
// speedup vs baseline: 1.1141x; 1.0006x over previous
#include <cuda_runtime.h>
#include <cuda_bf16.h>
#include <math.h>

// ---------------- problem constants ----------------
#define BATCH   4
#define LSEQ    1024
#define NMELS   80
#define DMODEL  512
#define NLAYER  6
#define DSTATE  16
#define DINNER  1024
#define DTRANK  32
#define DCONV   4
#define NROWS   (BATCH * LSEQ)          // 4096

// ---------------- scratch (static device memory; no allocation) ----------------
__device__ float g_h   [NROWS * DMODEL];
__device__ float g_xn  [NROWS * DMODEL];
__device__ float g_xr  [NROWS * 2 * DINNER];
__device__ float g_u   [NROWS * DINNER];
__device__ float g_xdbl[NROWS * 64];
__device__ float g_delta[NROWS * DINNER];
__device__ float g_y   [NROWS * DINNER];

// =====================================================================
// Big NT SGEMM: C[m,n] = sum_k A[m,k] * W[n,k]
// 128x128 tile, k-block 8, 256 threads, 8x8 microtile, LDS.128 fragments,
// double-buffered smem. Requires M%128==0, N%128==0, K%8==0.
// epilogue: v = acc (+bias[n]) (+addsrc[m*ldc+n]); act==1 -> softplus
// =====================================================================
__global__ __launch_bounds__(256)
void gemm_nt_big(const float* __restrict__ A, int lda,
                 const float* __restrict__ W, int ldw,
                 float* __restrict__ C, int ldc,
                 int K,
                 const float* __restrict__ bias,
                 const float* __restrict__ addsrc,
                 int act)
{
    __shared__ float As[2][8][132];   // k-major, padded (132%4==0 keeps 16B align)
    __shared__ float Bs[2][8][132];

    const int tid  = threadIdx.x;
    const int r0   = blockIdx.y * 128;
    const int n0   = blockIdx.x * 128;
    const int lrow = tid >> 1;            // 0..127
    const int lk4  = (tid & 1) * 4;       // 0 or 4

    const float* Ap = A + (size_t)(r0 + lrow) * lda + lk4;
    const float* Wp = W + (size_t)(n0 + lrow) * ldw + lk4;

    const int ty8 = (tid >> 4) * 8;       // row offset in tile
    const int tx8 = (tid & 15) * 8;       // col offset in tile

    float acc[8][8];
#pragma unroll
    for (int i = 0; i < 8; i++)
#pragma unroll
        for (int j = 0; j < 8; j++) acc[i][j] = 0.f;

    // preload first tile
    {
        float4 av = *(const float4*)Ap;
        float4 bv = *(const float4*)Wp;
        As[0][lk4 + 0][lrow] = av.x; As[0][lk4 + 1][lrow] = av.y;
        As[0][lk4 + 2][lrow] = av.z; As[0][lk4 + 3][lrow] = av.w;
        Bs[0][lk4 + 0][lrow] = bv.x; Bs[0][lk4 + 1][lrow] = bv.y;
        Bs[0][lk4 + 2][lrow] = bv.z; Bs[0][lk4 + 3][lrow] = bv.w;
    }
    __syncthreads();

    int buf = 0;
    for (int kk = 0; kk < K; kk += 8) {
        const bool has_next = (kk + 8) < K;
        float4 anx, bnx;
        if (has_next) {
            anx = *(const float4*)(Ap + kk + 8);
            bnx = *(const float4*)(Wp + kk + 8);
        }

#pragma unroll
        for (int k = 0; k < 8; k++) {
            float a[8], b[8];
            *(float4*)&a[0] = *(const float4*)&As[buf][k][ty8];
            *(float4*)&a[4] = *(const float4*)&As[buf][k][ty8 + 4];
            *(float4*)&b[0] = *(const float4*)&Bs[buf][k][tx8];
            *(float4*)&b[4] = *(const float4*)&Bs[buf][k][tx8 + 4];
#pragma unroll
            for (int i = 0; i < 8; i++)
#pragma unroll
                for (int j = 0; j < 8; j++)
                    acc[i][j] = fmaf(a[i], b[j], acc[i][j]);
        }

        if (has_next) {
            const int nb = buf ^ 1;
            As[nb][lk4 + 0][lrow] = anx.x; As[nb][lk4 + 1][lrow] = anx.y;
            As[nb][lk4 + 2][lrow] = anx.z; As[nb][lk4 + 3][lrow] = anx.w;
            Bs[nb][lk4 + 0][lrow] = bnx.x; Bs[nb][lk4 + 1][lrow] = bnx.y;
            Bs[nb][lk4 + 2][lrow] = bnx.z; Bs[nb][lk4 + 3][lrow] = bnx.w;
        }
        __syncthreads();
        buf ^= 1;
    }

    // epilogue
#pragma unroll
    for (int i = 0; i < 8; i++) {
        const size_t off = (size_t)(r0 + ty8 + i) * ldc + n0 + tx8;
#pragma unroll
        for (int j = 0; j < 8; j++) {
            float v = acc[i][j];
            if (bias)   v += bias[n0 + tx8 + j];
            if (addsrc) v += addsrc[off + j];
            if (act == 1) v = (v > 20.f) ? v : log1pf(__expf(v));
            C[off + j] = v;
        }
    }
}

// ---------------- small NT SGEMM (64x64 tile) for N<128 cases ----------------
__global__ __launch_bounds__(256, 4)
void gemm_nt(const float* __restrict__ A, int lda,
             const float* __restrict__ W, int ldw,
             float* __restrict__ C, int ldc,
             int N, int K,
             const float* __restrict__ bias,
             const float* __restrict__ addsrc,
             int act)
{
    __shared__ float As[64][17];
    __shared__ float Bs[64][17];

    const int tid = threadIdx.x;
    const int r0  = blockIdx.y * 64;
    const int n0  = blockIdx.x * 64;
    const int ty4 = (tid >> 4) * 4;
    const int tx4 = (tid & 15) * 4;

    float acc[4][4];
#pragma unroll
    for (int i = 0; i < 4; i++)
#pragma unroll
        for (int j = 0; j < 4; j++) acc[i][j] = 0.f;

    for (int kk = 0; kk < K; kk += 16) {
#pragma unroll
        for (int p = 0; p < 4; p++) {
            int li  = tid + p * 256;
            int row = li >> 4;
            int col = li & 15;
            As[row][col] = A[(size_t)(r0 + row) * lda + kk + col];
            int nr = n0 + row;
            Bs[row][col] = (nr < N) ? W[(size_t)nr * ldw + kk + col] : 0.f;
        }
        __syncthreads();

#pragma unroll
        for (int k = 0; k < 16; k++) {
            float a0 = As[ty4 + 0][k], a1 = As[ty4 + 1][k];
            float a2 = As[ty4 + 2][k], a3 = As[ty4 + 3][k];
            float b0 = Bs[tx4 + 0][k], b1 = Bs[tx4 + 1][k];
            float b2 = Bs[tx4 + 2][k], b3 = Bs[tx4 + 3][k];
            acc[0][0] = fmaf(a0, b0, acc[0][0]); acc[0][1] = fmaf(a0, b1, acc[0][1]);
            acc[0][2] = fmaf(a0, b2, acc[0][2]); acc[0][3] = fmaf(a0, b3, acc[0][3]);
            acc[1][0] = fmaf(a1, b0, acc[1][0]); acc[1][1] = fmaf(a1, b1, acc[1][1]);
            acc[1][2] = fmaf(a1, b2, acc[1][2]); acc[1][3] = fmaf(a1, b3, acc[1][3]);
            acc[2][0] = fmaf(a2, b0, acc[2][0]); acc[2][1] = fmaf(a2, b1, acc[2][1]);
            acc[2][2] = fmaf(a2, b2, acc[2][2]); acc[2][3] = fmaf(a2, b3, acc[2][3]);
            acc[3][0] = fmaf(a3, b0, acc[3][0]); acc[3][1] = fmaf(a3, b1, acc[3][1]);
            acc[3][2] = fmaf(a3, b2, acc[3][2]); acc[3][3] = fmaf(a3, b3, acc[3][3]);
        }
        __syncthreads();
    }

#pragma unroll
    for (int i = 0; i < 4; i++) {
        int m = r0 + ty4 + i;
#pragma unroll
        for (int j = 0; j < 4; j++) {
            int n = n0 + tx4 + j;
            if (n < N) {
                float v = acc[i][j];
                if (bias)   v += bias[n];
                if (addsrc) v += addsrc[(size_t)m * ldc + n];
                if (act == 1) v = (v > 20.f) ? v : log1pf(__expf(v));
                C[(size_t)m * ldc + n] = v;
            }
        }
    }
}

// ---------------- RMSNorm over last dim (=512), one block per row ----------------
__global__ void rmsnorm_k(const float* __restrict__ x, const float* __restrict__ w,
                          float* __restrict__ o)
{
    const int row = blockIdx.x;
    const int tid = threadIdx.x;
    const float* xr = x + (size_t)row * DMODEL;
    float v0 = xr[tid];
    float v1 = xr[tid + 256];
    float s  = v0 * v0 + v1 * v1;
#pragma unroll
    for (int off = 16; off; off >>= 1) s += __shfl_xor_sync(0xffffffffu, s, off);
    __shared__ float ws[8];
    if ((tid & 31) == 0) ws[tid >> 5] = s;
    __syncthreads();
    if (tid < 32) {
        float t = (tid < 8) ? ws[tid] : 0.f;
#pragma unroll
        for (int off = 4; off; off >>= 1) t += __shfl_xor_sync(0xffffffffu, t, off);
        if (tid == 0) ws[0] = t;
    }
    __syncthreads();
    float scale = rsqrtf(ws[0] * (1.f / DMODEL) + 1e-5f);
    float* orow = o + (size_t)row * DMODEL;
    orow[tid]       = v0 * scale * w[tid];
    orow[tid + 256] = v1 * scale * w[tid + 256];
}

// ---------------- causal depthwise conv (k=4) + bias + silu ----------------
__global__ void conv_silu_k(const float* __restrict__ xr,
                            const float* __restrict__ cw,
                            const float* __restrict__ cb,
                            float* __restrict__ u)
{
    int g = blockIdx.x * blockDim.x + threadIdx.x;
    int d = g & (DINNER - 1);
    int t = (g >> 10) & (LSEQ - 1);
    int b = g >> 20;
    const float* base = xr + ((size_t)(b * LSEQ + t)) * (2 * DINNER) + d;
    float w0 = cw[d * 4 + 0], w1 = cw[d * 4 + 1], w2 = cw[d * 4 + 2], w3 = cw[d * 4 + 3];
    float acc = cb[d] + base[0] * w3;
    if (t >= 1) acc = fmaf(base[-(2 * DINNER)], w2, acc);
    if (t >= 2) acc = fmaf(base[-(4 * DINNER)], w1, acc);
    if (t >= 3) acc = fmaf(base[-(6 * DINNER)], w0, acc);
    u[g] = acc / (1.f + __expf(-acc));
}

// ---------------- selective scan ----------------
__global__ __launch_bounds__(256, 8)
void scan_k(const float* __restrict__ delta, const float* __restrict__ u,
            const float* __restrict__ xdbl,  const float* __restrict__ xr,
            const float* __restrict__ A_log, const float* __restrict__ Dp,
            float* __restrict__ y)
{
    int g  = blockIdx.x * 256 + threadIdx.x;
    int n  = g & 15;
    int bd = g >> 4;
    int d  = bd & (DINNER - 1);
    int b  = bd >> 10;

    const float a  = -__expf(A_log[d * DSTATE + n]);
    const float Dv = Dp[d];

    const float* dp = delta + ((size_t)b * LSEQ) * DINNER + d;
    const float* up = u     + ((size_t)b * LSEQ) * DINNER + d;
    const float* rp = xr    + ((size_t)b * LSEQ) * (2 * DINNER) + DINNER + d;
    const float* xp = xdbl  + ((size_t)b * LSEQ) * 64;
    float*       yp = y     + ((size_t)b * LSEQ) * DINNER + d;

    float h = 0.f;
#pragma unroll 2
    for (int t = 0; t < LSEQ; t++) {
        float dv = dp[(size_t)t << 10];
        float uv = up[(size_t)t << 10];
        float Bv = xp[t * 64 + 32 + n];
        float Cv = xp[t * 64 + 48 + n];
        float dA = __expf(dv * a);
        h = fmaf(dA, h, dv * Bv * uv);
        float p = h * Cv;
        p += __shfl_xor_sync(0xffffffffu, p, 8);
        p += __shfl_xor_sync(0xffffffffu, p, 4);
        p += __shfl_xor_sync(0xffffffffu, p, 2);
        p += __shfl_xor_sync(0xffffffffu, p, 1);
        if (n == 0) {
            float yv = fmaf(uv, Dv, p);
            float r  = rp[(size_t)t << 11];
            yv *= r / (1.f + __expf(-r));
            yp[(size_t)t << 10] = yv;
        }
    }
}

// ---------------- host driver ----------------
extern "C" void kernel_launch(void* const* d_in, const int* in_sizes, int n_in,
                              void* d_out, int out_size)
{
    const float* x        = (const float*)d_in[0];
    const float* in_w     = (const float*)d_in[1];
    const float* in_b     = (const float*)d_in[2];
    const float* norm_w   = (const float*)d_in[3];
    const float* inproj_w = (const float*)d_in[4];
    const float* conv_w   = (const float*)d_in[5];
    const float* conv_b   = (const float*)d_in[6];
    const float* xproj_w  = (const float*)d_in[7];
    const float* dt_w     = (const float*)d_in[8];
    const float* dt_b     = (const float*)d_in[9];
    const float* A_log    = (const float*)d_in[10];
    const float* Dp       = (const float*)d_in[11];
    const float* outproj_w= (const float*)d_in[12];
    const float* normf_w  = (const float*)d_in[13];
    const float* out_w    = (const float*)d_in[14];
    float* out = (float*)d_out;

    float *h, *xn, *xrb, *u, *xdbl, *delta, *y;
    cudaGetSymbolAddress((void**)&h,     g_h);
    cudaGetSymbolAddress((void**)&xn,    g_xn);
    cudaGetSymbolAddress((void**)&xrb,   g_xr);
    cudaGetSymbolAddress((void**)&u,     g_u);
    cudaGetSymbolAddress((void**)&xdbl,  g_xdbl);
    cudaGetSymbolAddress((void**)&delta, g_delta);
    cudaGetSymbolAddress((void**)&y,     g_y);

    const dim3 blk(256);
    const int MB128 = NROWS / 128;   // 32 row-blocks for big gemm
    const int MB64  = NROWS / 64;    // 64 row-blocks for small gemm

    // input projection: h = x @ in_w^T + in_b  (M=4096, N=512, K=80) — big gemm
    gemm_nt_big<<<dim3(DMODEL / 128, MB128), blk>>>(x, NMELS, in_w, NMELS,
                                                    h, DMODEL, NMELS,
                                                    in_b, nullptr, 0);

    for (int i = 0; i < NLAYER; i++) {
        rmsnorm_k<<<NROWS, 256>>>(h, norm_w + (size_t)i * DMODEL, xn);

        // inproj: (4096 x 2048, K=512)
        gemm_nt_big<<<dim3(2 * DINNER / 128, MB128), blk>>>(xn, DMODEL,
            inproj_w + (size_t)i * 2 * DINNER * DMODEL, DMODEL,
            xrb, 2 * DINNER, DMODEL, nullptr, nullptr, 0);

        conv_silu_k<<<(NROWS * DINNER) / 256, 256>>>(xrb,
            conv_w + (size_t)i * DINNER * DCONV, conv_b + (size_t)i * DINNER, u);

        // xproj: (4096 x 64, K=1024) — N too small for big tile
        gemm_nt<<<dim3(1, MB64), blk>>>(u, DINNER,
            xproj_w + (size_t)i * 64 * DINNER, DINNER,
            xdbl, 64, 64, DINNER, nullptr, nullptr, 0);

        // delta = softplus(dt @ dt_w^T + dt_b)  (4096 x 1024, K=32)
        gemm_nt_big<<<dim3(DINNER / 128, MB128), blk>>>(xdbl, 64,
            dt_w + (size_t)i * DINNER * DTRANK, DTRANK,
            delta, DINNER, DTRANK,
            dt_b + (size_t)i * DINNER, nullptr, 1);

        scan_k<<<(NROWS * DSTATE) / 256, 256>>>(delta, u, xdbl, xrb,
            A_log + (size_t)i * DINNER * DSTATE, Dp + (size_t)i * DINNER, y);

        // outproj + residual: (4096 x 512, K=1024)
        gemm_nt_big<<<dim3(DMODEL / 128, MB128), blk>>>(y, DINNER,
            outproj_w + (size_t)i * DMODEL * DINNER, DINNER,
            h, DMODEL, DINNER, nullptr, h, 0);
    }

    rmsnorm_k<<<NROWS, 256>>>(h, normf_w, xn);
    // final: (4096 x 80, K=512) — small gemm (N=80)
    gemm_nt<<<dim3((NMELS + 63) / 64, MB64), blk>>>(xn, DMODEL, out_w, DMODEL,
                                                    out, NMELS, NMELS, DMODEL,
                                                    nullptr, nullptr, 0);
}